// round 6
// baseline (speedup 1.0000x reference)
#include <cuda_runtime.h>
#include <cuda_fp16.h>

#define D      128
#define H0     64
#define W0     96
#define NPIX0  (H0*W0)        // 6144
#define NPIX_T 8160           // 6144+1536+384+96

__device__ __align__(16) __half g_f1h[NPIX_T * D];   // fp16 channel-last, all levels
__device__ __align__(16) __half g_f2h[NPIX_T * D];   // fp16 channel-last, all levels
__device__ float  g_crd [NPIX_T * 2];
__device__ float  g_tmpA[5376 * 2];                  // x-resized coords, levels 1-3

__constant__ int c_HL[4] = {64, 32, 16, 8};
__constant__ int c_WL[4] = {96, 48, 24, 12};
__constant__ int c_PO[4] = {0, 6144, 7680, 8064};
__constant__ int c_OO[4] = {0, 81*6144, 81*7680, 81*8064};

// ---------------------------------------------------------------------------
// Kernel 1: transpose (D,HW)->(HW,D) to fp16 for both maps + coordsA.
// Loads: one LDG.128 per thread. Stores: coalesced 2B fp16.
// ---------------------------------------------------------------------------
#define TR_BLOCKS 1536          // 192 px-tiles x 4 d-tiles x 2 maps
#define CA_ELEMS  (2*NPIX0 + 5376*2)
#define CA_BLOCKS ((CA_ELEMS + 255)/256)

__global__ void __launch_bounds__(256) k_prep(const float* __restrict__ f1,
                                              const float* __restrict__ f2,
                                              const float* __restrict__ crd) {
    int b = blockIdx.x;
    if (b < TR_BLOCKS) {
        __shared__ float tile[32 * 33];
        int bx = b % 192;
        int by = (b / 192) & 3;
        int z  = b / 768;
        const float* src = z ? f2 : f1;
        int p0 = bx * 32, d0 = by * 32;
        int tx  = threadIdx.x & 31, ty = threadIdx.x >> 5;
        // load: thread -> (drow = t>>3, px4 = t&7), one float4
        int drow = threadIdx.x >> 3;
        int px4  = threadIdx.x & 7;
        float4 v = *(const float4*)(src + (size_t)(d0 + drow) * NPIX0 + p0 + px4 * 4);
        tile[drow * 33 + px4 * 4 + 0] = v.x;
        tile[drow * 33 + px4 * 4 + 1] = v.y;
        tile[drow * 33 + px4 * 4 + 2] = v.z;
        tile[drow * 33 + px4 * 4 + 3] = v.w;
        __syncthreads();
        __half* dst = z ? g_f2h : g_f1h;
        #pragma unroll
        for (int i = 0; i < 4; i++) {
            int p = p0 + ty + 8*i;
            int d = d0 + tx;
            dst[(size_t)p * D + d] = __float2half(tile[tx * 33 + ty + 8*i]);
        }
        return;
    }
    int idx = (b - TR_BLOCKS) * 256 + threadIdx.x;
    if (idx < 2 * NPIX0) {
        int q = idx >> 1, ax = idx & 1;
        g_crd[idx] = crd[ax * NPIX0 + q];
        return;
    }
    idx -= 2 * NPIX0;
    if (idx >= 5376 * 2) return;
    int p = idx >> 1, ax = idx & 1;
    int l, base;
    if      (p < 3072) { l = 1; base = 0;    }
    else if (p < 4608) { l = 2; base = 3072; }
    else               { l = 3; base = 4608; }
    int q  = p - base;
    int Wl = c_WL[l];
    int h  = q / Wl, w = q % Wl;
    float s   = (float)(1 << l);
    float cxx = (w + 0.5f) * s - 0.5f;
    int j0 = max(0,    (int)ceilf (cxx - s));
    int j1 = min(W0-1, (int)floorf(cxx + s));
    float sum = 0.f, acc = 0.f;
    for (int i = j0; i <= j1; i++) {
        float wgt = 1.f - fabsf(i - cxx) / s;
        sum += wgt;
        acc += wgt * crd[ax * NPIX0 + h * W0 + i];
    }
    g_tmpA[p * 2 + ax] = acc / sum;
}

// ---------------------------------------------------------------------------
// Kernel 2: pooled levels 1..3 (compile-time-unrolled taps) + coordsB.
// ---------------------------------------------------------------------------
#define POOL_N   (2016 * D)
#define PL_BLOCKS ((2 * POOL_N) / 256)
#define CB_ELEMS  (2016 * 2)

template<int F>
__device__ __forceinline__ float poolh(const __half* __restrict__ src, int h, int w, int d) {
    float acc = 0.f;
    #pragma unroll
    for (int i = 0; i < F; i++)
        #pragma unroll
        for (int j = 0; j < F; j++)
            acc += __half2float(src[(size_t)((h*F + i) * W0 + (w*F + j)) * D + d]);
    return acc * (1.0f / (F * F));
}

__global__ void __launch_bounds__(256) k_pool_coords() {
    int b = blockIdx.x;
    if (b < PL_BLOCKS) {
        int idx = b * 256 + threadIdx.x;
        int m = (idx >= POOL_N);
        int q = idx - m * POOL_N;
        int d  = q & (D - 1);
        int pl = q >> 7;
        int l, pbase;
        if      (pl < 1536) { l = 1; pbase = 0;    }
        else if (pl < 1920) { l = 2; pbase = 1536; }
        else                { l = 3; pbase = 1920; }
        int pp = pl - pbase;
        int Wl = c_WL[l];
        int w  = pp % Wl, h = pp / Wl;
        __half* arr = m ? g_f2h : g_f1h;
        float acc;
        if      (l == 1) acc = poolh<2>(arr, h, w, d);
        else if (l == 2) acc = poolh<4>(arr, h, w, d);
        else             acc = poolh<8>(arr, h, w, d);
        arr[(size_t)(c_PO[l] + pp) * D + d] = __float2half(acc);
        return;
    }
    int idx = (b - PL_BLOCKS) * 256 + threadIdx.x;
    if (idx >= CB_ELEMS) return;
    int p = idx >> 1, ax = idx & 1;
    int l, base, abase;
    if      (p < 1536) { l = 1; base = 0;    abase = 0;    }
    else if (p < 1920) { l = 2; base = 1536; abase = 3072; }
    else               { l = 3; base = 1920; abase = 4608; }
    int q  = p - base;
    int Wl = c_WL[l];
    int h  = q / Wl, w = q % Wl;
    float s   = (float)(1 << l);
    float cyy = (h + 0.5f) * s - 0.5f;
    int j0 = max(0,    (int)ceilf (cyy - s));
    int j1 = min(H0-1, (int)floorf(cyy + s));
    float sum = 0.f, acc = 0.f;
    for (int j = j0; j <= j1; j++) {
        float wgt = 1.f - fabsf(j - cyy) / s;
        sum += wgt;
        acc += wgt * g_tmpA[(abase + j * Wl + w) * 2 + ax];
    }
    g_crd[(c_PO[l] + q) * 2 + ax] = acc / (sum * s);
}

// ---------------------------------------------------------------------------
// Kernel 3: fused local correlation. Warp <-> pixel; 8-lane dot groups,
// 16 channels per lane; window offsets precomputed per warp into SMEM.
// ---------------------------------------------------------------------------
#define TILE 8
__device__ __forceinline__ float dot8h(float4 a0, float4 a1, float4 hv) {
    const __half2* h = (const __half2*)&hv;
    float2 v0 = __half22float2(h[0]);
    float2 v1 = __half22float2(h[1]);
    float2 v2 = __half22float2(h[2]);
    float2 v3 = __half22float2(h[3]);
    return a0.x*v0.x + a0.y*v0.y + a0.z*v1.x + a0.w*v1.y
         + a1.x*v2.x + a1.y*v2.y + a1.z*v3.x + a1.w*v3.y;
}

__global__ void __launch_bounds__(256) k_corr_all(float* __restrict__ out) {
    int b = blockIdx.x;
    int l, tbase;
    if      (b < 768)  { l = 0; tbase = 0;    }
    else if (b < 960)  { l = 1; tbase = 768;  }
    else if (b < 1008) { l = 2; tbase = 960;  }
    else               { l = 3; tbase = 1008; }
    int Hl = c_HL[l], Wl = c_WL[l];
    int pixoff = c_PO[l];
    int HW = Hl * Wl;
    int pix0 = (b - tbase) * TILE;

    int tid   = threadIdx.x;
    int lane  = tid & 31, warp = tid >> 5;
    int lane8 = lane & 7, grp = lane >> 3;

    __shared__ float gsh[TILE * 100];
    __shared__ int   osh[TILE * 100];
    __shared__ float fxs[TILE], fys[TILE];
    __shared__ int   bxs[TILE], bys[TILE];

    int pix = pix0 + warp;

    // f1 (fp16) -> fp32 registers: channels [lane8*8,+8) and [64+lane8*8,+8)
    const __half* f1row = g_f1h + (size_t)(pixoff + pix) * D;
    float4 ha = *(const float4*)(f1row + lane8 * 8);
    float4 hb = *(const float4*)(f1row + 64 + lane8 * 8);
    float4 a0, a1, a2, a3;
    {
        const __half2* pa = (const __half2*)&ha;
        float2 q0 = __half22float2(pa[0]), q1 = __half22float2(pa[1]);
        float2 q2 = __half22float2(pa[2]), q3 = __half22float2(pa[3]);
        a0 = make_float4(q0.x, q0.y, q1.x, q1.y);
        a1 = make_float4(q2.x, q2.y, q3.x, q3.y);
        const __half2* pb = (const __half2*)&hb;
        q0 = __half22float2(pb[0]); q1 = __half22float2(pb[1]);
        q2 = __half22float2(pb[2]); q3 = __half22float2(pb[3]);
        a2 = make_float4(q0.x, q0.y, q1.x, q1.y);
        a3 = make_float4(q2.x, q2.y, q3.x, q3.y);
    }

    float cx = 0.f, cy = 0.f;
    if (lane == 0) {
        cx = g_crd[(pixoff + pix) * 2];
        cy = g_crd[(pixoff + pix) * 2 + 1];
    }
    cx = __shfl_sync(0xffffffffu, cx, 0);
    cy = __shfl_sync(0xffffffffu, cy, 0);
    float flx = floorf(cx), fly = floorf(cy);
    int bx = (int)flx, by = (int)fly;
    if (lane == 0) {
        bxs[warp] = bx; bys[warp] = by;
        fxs[warp] = cx - flx; fys[warp] = cy - fly;
    }

    // precompute clamped window offsets (in halves, incl. *D) for all 100 pos
    int* osh100 = osh + warp * 100;
    #pragma unroll
    for (int r = 0; r < 4; r++) {
        int pos = lane + r * 32;
        if (pos < 100) {
            int u = (pos * 205) >> 11;       // /10
            int t = pos - u * 10;            // %10
            int px = min(max(bx + t - 4, 0), Wl - 1);
            int py = min(max(by + u - 4, 0), Hl - 1);
            osh100[pos] = (py * Wl + px) * D;
        }
    }
    __syncwarp();

    const __half* f2lane = g_f2h + (size_t)pixoff * D + lane8 * 8;
    float* gsh100 = gsh + warp * 100;

    #pragma unroll 5
    for (int i = 0; i < 25; i++) {
        int pos = i * 4 + grp;
        int off = osh100[pos];               // broadcast LDS
        const float4* r0 = (const float4*)(f2lane + off);
        float4 h0 = r0[0];
        float4 h1 = r0[8];                   // +64 channels
        float s = dot8h(a0, a1, h0) + dot8h(a2, a3, h1);
        s += __shfl_xor_sync(0xffffffffu, s, 4);
        s += __shfl_xor_sync(0xffffffffu, s, 2);
        s += __shfl_xor_sync(0xffffffffu, s, 1);
        if (lane8 == 0) gsh100[pos] = s;
    }
    __syncthreads();

    #pragma unroll
    for (int idx = tid; idx < 81 * TILE; idx += 256) {
        int k = idx >> 3;
        int j = idx & (TILE - 1);
        int adx = k / 9;
        int bdy = k - adx * 9;
        int t0 = bxs[j] + adx - 4;
        int u0 = bys[j] + bdy - 4;
        float wx1 = (t0 < 0 || t0 >= Wl - 1) ? 0.f : fxs[j];
        float wy1 = (u0 < 0 || u0 >= Hl - 1) ? 0.f : fys[j];
        float wx0 = 1.f - wx1, wy0 = 1.f - wy1;
        const float* g = gsh + j * 100 + bdy * 10 + adx;
        float c = wy0 * (wx0 * g[0]  + wx1 * g[1])
                + wy1 * (wx0 * g[10] + wx1 * g[11]);
        out[c_OO[l] + k * HW + pix0 + j] = c * 0.08838834764831845f; // 1/sqrt(128)
    }
}

// ---------------------------------------------------------------------------
extern "C" void kernel_launch(void* const* d_in, const int* in_sizes, int n_in,
                              void* d_out, int out_size) {
    const float* f1  = (const float*)d_in[0];
    const float* f2  = (const float*)d_in[1];
    const float* crd = (const float*)d_in[2];
    float* out = (float*)d_out;

    k_prep<<<TR_BLOCKS + CA_BLOCKS, 256>>>(f1, f2, crd);
    k_pool_coords<<<PL_BLOCKS + (CB_ELEMS + 255)/256, 256>>>();
    k_corr_all<<<1020, 256>>>(out);
}